// round 7
// baseline (speedup 1.0000x reference)
#include <cuda_runtime.h>

#define L  4096
#define V  50257
#define H1 30
#define H2 50
#define G1 120   // 4*H1
#define G2 200   // 4*H2

// scratch (device globals: no allocation allowed)
__device__ float g_gx1p[L * 128];   // [t][cell*4 + gate], row padded to 128
__device__ float g_h2  [L * H2];
__device__ float g_wf  [G2 * H1];   // W_ih2 @ W1
__device__ float g_bf  [G2];        // W_ih2 @ bl1 + b_ih2 + b_hh2

typedef unsigned long long u64;

__device__ __forceinline__ u64 pk2(float lo, float hi) {
    u64 r; asm("mov.b64 %0, {%1, %2};" : "=l"(r) : "f"(lo), "f"(hi)); return r;
}
__device__ __forceinline__ u64 ffma2(u64 a, u64 b, u64 c) {
    u64 d; asm("fma.rn.f32x2 %0, %1, %2, %3;" : "=l"(d) : "l"(a), "l"(b), "l"(c)); return d;
}
__device__ __forceinline__ u64 fadd2(u64 a, u64 b) {
    u64 d; asm("add.rn.f32x2 %0, %1, %2;" : "=l"(d) : "l"(a), "l"(b)); return d;
}
__device__ __forceinline__ float hsum2(u64 a) {
    float x, y; asm("mov.b64 {%0, %1}, %2;" : "=f"(x), "=f"(y) : "l"(a)); return x + y;
}

__device__ __forceinline__ float fexp(float x) {
    float y; asm("ex2.approx.f32 %0, %1;" : "=f"(y) : "f"(x * 1.4426950408889634f)); return y;
}
__device__ __forceinline__ float frcp(float x) {
    float y; asm("rcp.approx.f32 %0, %1;" : "=f"(y) : "f"(x)); return y;
}
__device__ __forceinline__ float sigm(float x)   { return frcp(1.0f + fexp(-x)); }
__device__ __forceinline__ float tanh_f(float x) { return 1.0f - 2.0f * frcp(fexp(2.0f * x) + 1.0f); }

// ---------------------------------------------------------------------------
// K1: gx1p[t][c*4+g] = emb[x[t]] . w_ih1[g*30+c] + b_ih1 + b_hh1 (pad -> 0)
// ---------------------------------------------------------------------------
__global__ void k_gx1(const int* __restrict__ x, const float* __restrict__ emb,
                      const float* __restrict__ w_ih1, const float* __restrict__ b_ih1,
                      const float* __restrict__ b_hh1) {
    int idx = blockIdx.x * blockDim.x + threadIdx.x;
    if (idx >= L * 128) return;
    int t = idx >> 7, jj = idx & 127;
    int c = jj >> 2, g = jj & 3;
    float s = 0.0f;
    if (c < H1) {
        int j = g * H1 + c;
        const float* er = emb + (long)x[t] * H1;
        const float* wr = w_ih1 + j * H1;
        s = b_ih1[j] + b_hh1[j];
#pragma unroll
        for (int k = 0; k < H1; k++) s += er[k] * wr[k];
    }
    g_gx1p[idx] = s;
}

// ---------------------------------------------------------------------------
// K2: fuse Wf = W_ih2 @ W1, bf = W_ih2 @ bl1 + b_ih2 + b_hh2
// ---------------------------------------------------------------------------
__global__ void k_fuse(const float* __restrict__ w_ih2, const float* __restrict__ w1,
                       const float* __restrict__ bl1, const float* __restrict__ b_ih2,
                       const float* __restrict__ b_hh2) {
    int idx = blockIdx.x * blockDim.x + threadIdx.x;
    if (idx < G2 * H1) {
        int j = idx / H1, m = idx % H1;
        float s = 0.0f;
#pragma unroll
        for (int k = 0; k < H2; k++) s += w_ih2[j * H2 + k] * w1[k * H1 + m];
        g_wf[idx] = s;
    }
    if (idx < G2) {
        float s = b_ih2[idx] + b_hh2[idx];
#pragma unroll
        for (int k = 0; k < H2; k++) s += w_ih2[idx * H2 + k] * bl1[k];
        g_bf[idx] = s;
    }
}

// ---------------------------------------------------------------------------
// K3: ONE CTA, 8 warps, 1 __syncthreads/step, all handoff through shared.
//   warp 7   : entire layer1 — lane=cell, all 4 gates in-lane (no shfl).
//   warps 0-6: layer2 gates — lane = gate*8+sub, cell = wid*8+sub.
// Iteration n: warp7 produces h1[n] (reads h1s[n&1]=h1[n-1], writes
// h1s[(n+1)&1]); warps0-6 produce h2[n-1] (read h1s[n&1], h2s[n&1]=h2[n-2],
// write h2s[(n+1)&1]).
// ---------------------------------------------------------------------------
__global__ void __launch_bounds__(256, 1) k_scan(const float* __restrict__ w_hh1,
                                                 const float* __restrict__ w_hh2) {
    __shared__ __align__(16) float h1s[2][32];
    __shared__ __align__(16) float h2s[2][56];
    const int tid = threadIdx.x, wid = tid >> 5, lane = tid & 31;

    // ---------------- per-role setup ----------------
    // layer1 (warp 7)
    u64 wa[4][15];
    float4 gxbuf[2];
    // layer2 (warps 0-6)
    u64 wf[15], wc[25];
    float bfv = 0.0f;
    const int gate = lane >> 3, sub = lane & 7;
    const int cell2 = wid * 8 + sub;
    const bool isL1 = (wid == 7);
    const bool valid2 = !isL1 && (cell2 < H2);
    const bool valid1 = isL1 && (lane < H1);

    if (isL1) {
#pragma unroll
        for (int g = 0; g < 4; g++)
#pragma unroll
            for (int m = 0; m < 15; m++) wa[g][m] = 0;
        if (valid1) {
#pragma unroll
            for (int g = 0; g < 4; g++) {
                const float* row = w_hh1 + (g * H1 + lane) * H1;
#pragma unroll
                for (int m = 0; m < 15; m++) wa[g][m] = pk2(row[2 * m], row[2 * m + 1]);
            }
        }
        gxbuf[0] = __ldg((const float4*)&g_gx1p[0 * 128 + lane * 4]);
        gxbuf[1] = __ldg((const float4*)&g_gx1p[1 * 128 + lane * 4]);
    } else {
#pragma unroll
        for (int m = 0; m < 15; m++) wf[m] = 0;
#pragma unroll
        for (int m = 0; m < 25; m++) wc[m] = 0;
        if (valid2) {
            int j = gate * H2 + cell2;
            const float* w = g_wf + j * H1;
#pragma unroll
            for (int m = 0; m < 15; m++) wf[m] = pk2(w[2 * m], w[2 * m + 1]);
            const float* w2r = w_hh2 + j * H2;
#pragma unroll
            for (int m = 0; m < 25; m++) wc[m] = pk2(w2r[2 * m], w2r[2 * m + 1]);
            bfv = g_bf[j];
        }
    }
    if (tid < 32) { h1s[0][tid] = 0.0f; h1s[1][tid] = 0.0f; }
    if (tid >= 64 && tid < 120) { h2s[0][tid - 64] = 0.0f; h2s[1][tid - 64] = 0.0f; }
    float cst = 0.0f;
    __syncthreads();

    for (int n = 0; n <= L; n++) {
        if (isL1) {
            if (n < L) {
                float4 gx = gxbuf[n & 1];
                if (n + 2 < L)
                    gxbuf[n & 1] = __ldg((const float4*)&g_gx1p[(n + 2) * 128 + lane * 4]);
                const u64* hp = (const u64*)h1s[n & 1];
                u64 hv[15];
                {
                    const ulonglong2* h2p = (const ulonglong2*)hp;
#pragma unroll
                    for (int m = 0; m < 7; m++) { ulonglong2 t2 = h2p[m]; hv[2*m] = t2.x; hv[2*m+1] = t2.y; }
                    hv[14] = hp[14];
                }
                u64 a0[4], a1[4];
#pragma unroll
                for (int g = 0; g < 4; g++) { a0[g] = 0; a1[g] = 0; }
#pragma unroll
                for (int g = 0; g < 4; g++) {
#pragma unroll
                    for (int m = 0; m < 15; m += 2) a0[g] = ffma2(wa[g][m], hv[m], a0[g]);
#pragma unroll
                    for (int m = 1; m < 15; m += 2) a1[g] = ffma2(wa[g][m], hv[m], a1[g]);
                }
                float si = gx.x + hsum2(fadd2(a0[0], a1[0]));
                float sf = gx.y + hsum2(fadd2(a0[1], a1[1]));
                float sg = gx.z + hsum2(fadd2(a0[2], a1[2]));
                float so = gx.w + hsum2(fadd2(a0[3], a1[3]));
                float ai = sigm(si), af = sigm(sf), ag = tanh_f(sg), ao = sigm(so);
                cst = af * cst + ai * ag;
                float h = valid1 ? ao * tanh_f(cst) : 0.0f;
                h1s[(n + 1) & 1][lane] = h;
            }
        } else if (n >= 1) {
            const u64* hq1 = (const u64*)h1s[n & 1];          // h1[n-1]
            const u64* hq2 = (const u64*)h2s[n & 1];          // h2[n-2]
            const ulonglong2* hv1 = (const ulonglong2*)hq1;
            const ulonglong2* hv2 = (const ulonglong2*)hq2;
            u64 a0 = 0, a1 = 0, a2 = 0, a3 = 0;
#pragma unroll
            for (int m = 0; m < 7; m++) {
                ulonglong2 hh = hv1[m];
                a0 = ffma2(wf[2 * m],     hh.x, a0);
                a1 = ffma2(wf[2 * m + 1], hh.y, a1);
            }
            a0 = ffma2(wf[14], hq1[14], a0);
#pragma unroll
            for (int m = 0; m < 12; m++) {
                ulonglong2 hh = hv2[m];
                a2 = ffma2(wc[2 * m],     hh.x, a2);
                a3 = ffma2(wc[2 * m + 1], hh.y, a3);
            }
            a2 = ffma2(wc[24], hq2[24], a2);
            float s = bfv + hsum2(fadd2(fadd2(a0, a1), fadd2(a2, a3)));
            float act = (gate == 2) ? tanh_f(s) : sigm(s);
            float y1 = __shfl_xor_sync(0xffffffffu, act, 8);
            float y2 = __shfl_xor_sync(0xffffffffu, act, 16);
            float y3 = __shfl_xor_sync(0xffffffffu, act, 24);
            float ai, af, ag, ao;
            if      (gate == 0) { ai = act; af = y1;  ag = y2;  ao = y3;  }
            else if (gate == 1) { ai = y1;  af = act; ag = y3;  ao = y2;  }
            else if (gate == 2) { ai = y2;  af = y3;  ag = act; ao = y1;  }
            else                { ai = y3;  af = y2;  ag = y1;  ao = act; }
            cst = af * cst + ai * ag;
            float h = ao * tanh_f(cst);
            if (gate == 0 && valid2) {
                h2s[(n + 1) & 1][cell2] = h;
                g_h2[(n - 1) * H2 + cell2] = h;
            }
        }
        __syncthreads();
    }
}

// ---------------------------------------------------------------------------
// K4: out[t][v] = h2[t] . w2[v] + bl2[v]
// K-split: lane pair (even,odd) shares one v; even takes k[0:24), odd k[24:50).
// Combine with one shfl_xor(1). 256 thr/block -> ~50 regs -> 2x occupancy.
// grid: (ceil(V/128), 16)
// ---------------------------------------------------------------------------
__global__ void __launch_bounds__(256) k_out(const float* __restrict__ w2,
                                             const float* __restrict__ bl2,
                                             float* __restrict__ out) {
    __shared__ __align__(16) float h_sh[32 * 56];
    const int half = threadIdx.x & 1;
    const int vloc = threadIdx.x >> 1;          // 0..127
    const int v = blockIdx.x * 128 + vloc;
    const bool active = (v < V);
    const int kbase = half * 24;                // 0 or 24

    u64 wr[13];
    float bias = 0.0f;
#pragma unroll
    for (int m = 0; m < 13; m++) wr[m] = 0;
    if (active) {
        const float* w = w2 + (long)v * H2 + kbase;
#pragma unroll
        for (int m = 0; m < 12; m++) wr[m] = pk2(w[2 * m], w[2 * m + 1]);
        if (half) wr[12] = pk2(w[24], w[25]);   // k=48,49
        bias = bl2[v];
    }

    int tbeg = blockIdx.y * (L / 16);
    int tend = tbeg + (L / 16);
    for (int t0 = tbeg; t0 < tend; t0 += 32) {
        __syncthreads();
        for (int i = threadIdx.x; i < 32 * H2; i += blockDim.x) {
            int r = i / H2, col = i - r * H2;
            h_sh[r * 56 + col] = g_h2[(t0 + r) * H2 + col];
        }
        __syncthreads();
#pragma unroll 4
        for (int tt = 0; tt < 32; tt++) {
            const u64* hq = (const u64*)(h_sh + tt * 56 + kbase);
            const ulonglong2* hv = (const ulonglong2*)hq;
            u64 a0 = 0, a1 = 0, a2 = 0, a3 = 0;
#pragma unroll
            for (int m = 0; m < 3; m++) {
                ulonglong2 hh = hv[2 * m];
                a0 = ffma2(wr[4 * m],     hh.x, a0);
                a1 = ffma2(wr[4 * m + 1], hh.y, a1);
                ulonglong2 hh2 = hv[2 * m + 1];
                a2 = ffma2(wr[4 * m + 2], hh2.x, a2);
                a3 = ffma2(wr[4 * m + 3], hh2.y, a3);
            }
            a0 = ffma2(wr[12], hq[12], a0);
            float s = hsum2(fadd2(fadd2(a0, a1), fadd2(a2, a3)));
            s += __shfl_xor_sync(0xffffffffu, s, 1);
            if (active && half == 0)
                out[(long)(t0 + tt) * V + v] = s + bias;
        }
    }
}

// ---------------------------------------------------------------------------
extern "C" void kernel_launch(void* const* d_in, const int* in_sizes, int n_in,
                              void* d_out, int out_size) {
    const int*   x     = (const int*)  d_in[0];
    const float* emb   = (const float*)d_in[1];
    const float* w_ih1 = (const float*)d_in[2];
    const float* w_hh1 = (const float*)d_in[3];
    const float* b_ih1 = (const float*)d_in[4];
    const float* b_hh1 = (const float*)d_in[5];
    const float* w1    = (const float*)d_in[6];
    const float* bl1   = (const float*)d_in[7];
    const float* w_ih2 = (const float*)d_in[8];
    const float* w_hh2 = (const float*)d_in[9];
    const float* b_ih2 = (const float*)d_in[10];
    const float* b_hh2 = (const float*)d_in[11];
    const float* w2    = (const float*)d_in[12];
    const float* bl2   = (const float*)d_in[13];
    float* out = (float*)d_out;

    k_gx1 <<<(L * 128 + 255) / 256, 256>>>(x, emb, w_ih1, b_ih1, b_hh1);
    k_fuse<<<(G2 * H1 + 255) / 256, 256>>>(w_ih2, w1, bl1, b_ih2, b_hh2);
    k_scan<<<1, 256>>>(w_hh1, w_hh2);
    dim3 g5((V + 127) / 128, 16);
    k_out <<<g5, 256>>>(w2, bl2, out);
}

// round 11
// speedup vs baseline: 1.7063x; 1.7063x over previous
#include <cuda_runtime.h>

#define L  4096
#define V  50257
#define H1 30
#define H2 50
#define G1 120   // 4*H1
#define G2 200   // 4*H2

// scratch (device globals: no allocation allowed)
__device__ float g_gx1p[L * 128];   // [t][cell*4 + gate], row padded to 128
__device__ float g_h1r [L * 32];    // layer1 hidden ring, row padded to 32
__device__ float g_h2  [L * H2];
__device__ float g_wf  [G2 * H1];   // W_ih2 @ W1
__device__ float g_bf  [G2];        // W_ih2 @ bl1 + b_ih2 + b_hh2
__device__ int   g_prog;            // #steps of h1 published

typedef unsigned long long u64;

__device__ __forceinline__ u64 pk2(float lo, float hi) {
    u64 r; asm("mov.b64 %0, {%1, %2};" : "=l"(r) : "f"(lo), "f"(hi)); return r;
}
__device__ __forceinline__ u64 ffma2(u64 a, u64 b, u64 c) {
    u64 d; asm("fma.rn.f32x2 %0, %1, %2, %3;" : "=l"(d) : "l"(a), "l"(b), "l"(c)); return d;
}
__device__ __forceinline__ u64 fadd2(u64 a, u64 b) {
    u64 d; asm("add.rn.f32x2 %0, %1, %2;" : "=l"(d) : "l"(a), "l"(b)); return d;
}
__device__ __forceinline__ float hsum2(u64 a) {
    float x, y; asm("mov.b64 {%0, %1}, %2;" : "=f"(x), "=f"(y) : "l"(a)); return x + y;
}

__device__ __forceinline__ float fexp(float x) {
    float y; asm("ex2.approx.f32 %0, %1;" : "=f"(y) : "f"(x * 1.4426950408889634f)); return y;
}
__device__ __forceinline__ float frcp(float x) {
    float y; asm("rcp.approx.f32 %0, %1;" : "=f"(y) : "f"(x)); return y;
}
__device__ __forceinline__ float sigm(float x)   { return frcp(1.0f + fexp(-x)); }
__device__ __forceinline__ float tanh_f(float x) { return 1.0f - 2.0f * frcp(fexp(2.0f * x) + 1.0f); }

// ---------------------------------------------------------------------------
// K1: gx1p[t][c*4+g] = emb[x[t]] . w_ih1[g*30+c] + b_ih1 + b_hh1 (pad -> 0)
// Also resets the progress flag.
// ---------------------------------------------------------------------------
__global__ void k_gx1(const int* __restrict__ x, const float* __restrict__ emb,
                      const float* __restrict__ w_ih1, const float* __restrict__ b_ih1,
                      const float* __restrict__ b_hh1) {
    int idx = blockIdx.x * blockDim.x + threadIdx.x;
    if (idx == 0) g_prog = 0;
    if (idx >= L * 128) return;
    int t = idx >> 7, jj = idx & 127;
    int c = jj >> 2, g = jj & 3;
    float s = 0.0f;
    if (c < H1) {
        int j = g * H1 + c;
        const float* er = emb + (long)x[t] * H1;
        const float* wr = w_ih1 + j * H1;
        s = b_ih1[j] + b_hh1[j];
#pragma unroll
        for (int k = 0; k < H1; k++) s += er[k] * wr[k];
    }
    g_gx1p[idx] = s;
}

// ---------------------------------------------------------------------------
// K2: fuse Wf = W_ih2 @ W1, bf = W_ih2 @ bl1 + b_ih2 + b_hh2
// ---------------------------------------------------------------------------
__global__ void k_fuse(const float* __restrict__ w_ih2, const float* __restrict__ w1,
                       const float* __restrict__ bl1, const float* __restrict__ b_ih2,
                       const float* __restrict__ b_hh2) {
    int idx = blockIdx.x * blockDim.x + threadIdx.x;
    if (idx < G2 * H1) {
        int j = idx / H1, m = idx % H1;
        float s = 0.0f;
#pragma unroll
        for (int k = 0; k < H2; k++) s += w_ih2[j * H2 + k] * w1[k * H1 + m];
        g_wf[idx] = s;
    }
    if (idx < G2) {
        float s = b_ih2[idx] + b_hh2[idx];
#pragma unroll
        for (int k = 0; k < H2; k++) s += w_ih2[idx * H2 + k] * bl1[k];
        g_bf[idx] = s;
    }
}

// ---------------------------------------------------------------------------
// K3: two cooperating CTAs on two SMs (R4 structure).
//   blockIdx.x == 1 : layer1 — ONE warp, lane=cell, all 4 gates in-lane,
//                     publishes h1 + release flag every 8 steps.
//   blockIdx.x == 0 : layer2 — warps 0-6 gates; warp 7 maintains a 16-slot
//                     shared h1 ring. Batch prefetch every 8 steps, with the
//                     poll+LDG issued at n%8==0 and the STS commit at n%8==4,
//                     so no memory latency sits on the per-step barrier path.
// Layer2 at step n consumes ring[n%16] = h1[n], producing h2[n].
// ---------------------------------------------------------------------------
__global__ void __launch_bounds__(256, 1) k_scan(const float* __restrict__ w_hh1,
                                                 const float* __restrict__ w_hh2) {
    const int tid = threadIdx.x, wid = tid >> 5, lane = tid & 31;

    if (blockIdx.x == 1) {
        // ================= layer 1 : single warp =================
        if (wid != 0) return;
        __shared__ __align__(16) float h_sh[32];
        const int c = lane;
        const bool valid = (c < H1);

        u64 w[4][15];
#pragma unroll
        for (int g = 0; g < 4; g++)
#pragma unroll
            for (int m = 0; m < 15; m++) w[g][m] = 0;
        if (valid) {
#pragma unroll
            for (int g = 0; g < 4; g++) {
                const float* row = w_hh1 + (g * H1 + c) * H1;
#pragma unroll
                for (int m = 0; m < 15; m++) w[g][m] = pk2(row[2 * m], row[2 * m + 1]);
            }
        }
        h_sh[lane] = 0.0f;
        __syncwarp();

        float cst = 0.0f;
        float4 gxbuf[2];
        gxbuf[0] = __ldg((const float4*)&g_gx1p[0 * 128 + c * 4]);
        gxbuf[1] = __ldg((const float4*)&g_gx1p[1 * 128 + c * 4]);

        for (int n = 0; n < L; n++) {
            float4 gx = gxbuf[n & 1];
            if (n + 2 < L)
                gxbuf[n & 1] = __ldg((const float4*)&g_gx1p[(n + 2) * 128 + c * 4]);

            const u64* hp = (const u64*)h_sh;
            u64 hv[15];
            {
                const ulonglong2* h2p = (const ulonglong2*)h_sh;
#pragma unroll
                for (int m = 0; m < 7; m++) { ulonglong2 t2 = h2p[m]; hv[2*m] = t2.x; hv[2*m+1] = t2.y; }
                hv[14] = hp[14];
            }
            u64 a0[4], a1[4];
#pragma unroll
            for (int g = 0; g < 4; g++) { a0[g] = 0; a1[g] = 0; }
#pragma unroll
            for (int g = 0; g < 4; g++) {
#pragma unroll
                for (int m = 0; m < 15; m += 2) a0[g] = ffma2(w[g][m], hv[m], a0[g]);
#pragma unroll
                for (int m = 1; m < 15; m += 2) a1[g] = ffma2(w[g][m], hv[m], a1[g]);
            }
            float si = gx.x + hsum2(fadd2(a0[0], a1[0]));
            float sf = gx.y + hsum2(fadd2(a0[1], a1[1]));
            float sg = gx.z + hsum2(fadd2(a0[2], a1[2]));
            float so = gx.w + hsum2(fadd2(a0[3], a1[3]));
            float ai = sigm(si), af = sigm(sf), ag = tanh_f(sg), ao = sigm(so);
            cst = af * cst + ai * ag;
            float h = valid ? ao * tanh_f(cst) : 0.0f;
            __syncwarp();
            h_sh[lane] = h;
            g_h1r[n * 32 + lane] = h;
            __syncwarp();
            if ((n & 7) == 7) {
                __threadfence();
                if (lane == 0) {
                    int val = n + 1;
                    asm volatile("st.global.release.gpu.s32 [%0], %1;"
                                 :: "l"(&g_prog), "r"(val) : "memory");
                }
            }
        }
        return;
    }

    // ================= layer 2 : 8 warps =================
    __shared__ __align__(16) float h1ring[16][32];   // ring[k%16] = h1[k]
    __shared__ __align__(16) float h2s[2][56];
    const int gate = lane >> 3, sub = lane & 7;
    const bool isGate = (wid < 7);
    const int cell = wid * 8 + sub;
    const bool valid = isGate && (cell < H2);

    u64 wf[15], wc[25];
    float bfv = 0.0f;
#pragma unroll
    for (int m = 0; m < 15; m++) wf[m] = 0;
#pragma unroll
    for (int m = 0; m < 25; m++) wc[m] = 0;
    if (valid) {
        int j = gate * H2 + cell;
        const float* w = g_wf + j * H1;
#pragma unroll
        for (int m = 0; m < 15; m++) wf[m] = pk2(w[2 * m], w[2 * m + 1]);
        const float* w2r = w_hh2 + j * H2;
#pragma unroll
        for (int m = 0; m < 25; m++) wc[m] = pk2(w2r[2 * m], w2r[2 * m + 1]);
        bfv = g_bf[j];
    }
    if (tid < 56) { h2s[0][tid] = 0.0f; h2s[1][tid] = 0.0f; }

    // warmup: wait for layer1 to be 16 ahead, fill ring slots 0..15
    if (wid == 7) {
        int seen = 0;
        do { asm volatile("ld.global.acquire.gpu.s32 %0, [%1];"
                          : "=r"(seen) : "l"(&g_prog) : "memory"); } while (seen < 16);
        // 16 rows * 8 float4 = 128 float4, 4 per lane
#pragma unroll
        for (int q = 0; q < 4; q++) {
            int f = q * 32 + lane;            // float4 index
            int row = f >> 3, col = f & 7;
            ((float4*)h1ring[row])[col] = __ldg((const float4*)&g_h1r[row * 32 + col * 4]);
        }
    }
    __syncthreads();

    float cst = 0.0f;
    float4 pf0, pf1;          // warp7 in-flight prefetch registers
    int pfbase = 0;           // base row of pending batch
    for (int n = 0; n < L; n++) {
        if (isGate) {
            const u64* hq1 = (const u64*)h1ring[n & 15];      // h1[n]
            const u64* hq2 = (const u64*)h2s[n & 1];          // h2[n-1]
            const ulonglong2* hv1 = (const ulonglong2*)hq1;
            const ulonglong2* hv2 = (const ulonglong2*)hq2;
            u64 a0 = 0, a1 = 0, a2 = 0, a3 = 0;
#pragma unroll
            for (int m = 0; m < 7; m++) {
                ulonglong2 hh = hv1[m];
                a0 = ffma2(wf[2 * m],     hh.x, a0);
                a1 = ffma2(wf[2 * m + 1], hh.y, a1);
            }
            a0 = ffma2(wf[14], hq1[14], a0);
#pragma unroll
            for (int m = 0; m < 12; m++) {
                ulonglong2 hh = hv2[m];
                a2 = ffma2(wc[2 * m],     hh.x, a2);
                a3 = ffma2(wc[2 * m + 1], hh.y, a3);
            }
            a2 = ffma2(wc[24], hq2[24], a2);
            float s = bfv + hsum2(fadd2(fadd2(a0, a1), fadd2(a2, a3)));
            float act = (gate == 2) ? tanh_f(s) : sigm(s);
            float y1 = __shfl_xor_sync(0xffffffffu, act, 8);
            float y2 = __shfl_xor_sync(0xffffffffu, act, 16);
            float y3 = __shfl_xor_sync(0xffffffffu, act, 24);
            float ai, af, ag, ao;
            if      (gate == 0) { ai = act; af = y1;  ag = y2;  ao = y3;  }
            else if (gate == 1) { ai = y1;  af = act; ag = y3;  ao = y2;  }
            else if (gate == 2) { ai = y2;  af = y3;  ag = act; ao = y1;  }
            else                { ai = y3;  af = y2;  ag = y1;  ao = act; }
            cst = af * cst + ai * ag;
            float h = ao * tanh_f(cst);
            if (gate == 0 && valid) {
                h2s[(n + 1) & 1][cell] = h;
                g_h2[n * H2 + cell] = h;
            }
        } else {
            // warp 7: batched ring refill, latency split across two phases
            int ph = n & 7;
            if (ph == 0) {
                pfbase = n + 16;                    // rows n+16 .. n+23
                if (pfbase < L) {
                    int need = pfbase + 8 <= L ? pfbase + 8 : L;
                    int seen;
                    // poll until layer1 has published all rows of this batch
                    do { asm volatile("ld.global.acquire.gpu.s32 %0, [%1];"
                                      : "=r"(seen) : "l"(&g_prog) : "memory"); } while (seen < need);
                    // 8 rows * 8 float4 = 64 float4, 2 per lane
                    int f0 = lane, f1 = 32 + lane;
                    int r0 = pfbase + (f0 >> 3), c0 = f0 & 7;
                    int r1 = pfbase + (f1 >> 3), c1 = f1 & 7;
                    pf0 = (r0 < L) ? __ldg((const float4*)&g_h1r[r0 * 32 + c0 * 4])
                                   : make_float4(0.f, 0.f, 0.f, 0.f);
                    pf1 = (r1 < L) ? __ldg((const float4*)&g_h1r[r1 * 32 + c1 * 4])
                                   : make_float4(0.f, 0.f, 0.f, 0.f);
                }
            } else if (ph == 4) {
                if (pfbase < L) {
                    int f0 = lane, f1 = 32 + lane;
                    int r0 = pfbase + (f0 >> 3), c0 = f0 & 7;
                    int r1 = pfbase + (f1 >> 3), c1 = f1 & 7;
                    if (r0 < L) ((float4*)h1ring[r0 & 15])[c0] = pf0;
                    if (r1 < L) ((float4*)h1ring[r1 & 15])[c1] = pf1;
                }
            }
        }
        __syncthreads();
    }
}

// ---------------------------------------------------------------------------
// K4: out[t][v] = h2[t] . w2[v] + bl2[v]  (f32x2 FMA, LDS.128 h-tile)
// grid: (ceil(V/128), 16)
// ---------------------------------------------------------------------------
__global__ void k_out(const float* __restrict__ w2, const float* __restrict__ bl2,
                      float* __restrict__ out) {
    __shared__ __align__(16) float h_sh[32 * 56];
    int v = blockIdx.x * blockDim.x + threadIdx.x;
    bool active = (v < V);

    u64 wr[25];
    float bias = 0.0f;
    if (active) {
        const float* w = w2 + (long)v * H2;
#pragma unroll
        for (int m = 0; m < 25; m++) wr[m] = pk2(w[2 * m], w[2 * m + 1]);
        bias = bl2[v];
    }

    int tbeg = blockIdx.y * (L / 16);
    int tend = tbeg + (L / 16);
    for (int t0 = tbeg; t0 < tend; t0 += 32) {
        __syncthreads();
        for (int i = threadIdx.x; i < 32 * H2; i += blockDim.x) {
            int r = i / H2, col = i - r * H2;
            h_sh[r * 56 + col] = g_h2[(t0 + r) * H2 + col];
        }
        __syncthreads();
#pragma unroll 4
        for (int tt = 0; tt < 32; tt++) {
            const u64* hq = (const u64*)(h_sh + tt * 56);
            const ulonglong2* hv = (const ulonglong2*)hq;
            u64 a0 = 0, a1 = 0, a2 = 0, a3 = 0;
#pragma unroll
            for (int m = 0; m < 6; m++) {
                ulonglong2 hh = hv[2 * m];
                a0 = ffma2(wr[4 * m],     hh.x, a0);
                a1 = ffma2(wr[4 * m + 1], hh.y, a1);
                ulonglong2 hh2 = hv[2 * m + 1];
                a2 = ffma2(wr[4 * m + 2], hh2.x, a2);
                a3 = ffma2(wr[4 * m + 3], hh2.y, a3);
            }
            a0 = ffma2(wr[24], hq[24], a0);
            if (active)
                out[(long)(t0 + tt) * V + v] =
                    hsum2(fadd2(fadd2(a0, a1), fadd2(a2, a3))) + bias;
        }
    }
}

// ---------------------------------------------------------------------------
extern "C" void kernel_launch(void* const* d_in, const int* in_sizes, int n_in,
                              void* d_out, int out_size) {
    const int*   x     = (const int*)  d_in[0];
    const float* emb   = (const float*)d_in[1];
    const float* w_ih1 = (const float*)d_in[2];
    const float* w_hh1 = (const float*)d_in[3];
    const float* b_ih1 = (const float*)d_in[4];
    const float* b_hh1 = (const float*)d_in[5];
    const float* w1    = (const float*)d_in[6];
    const float* bl1   = (const float*)d_in[7];
    const float* w_ih2 = (const float*)d_in[8];
    const float* w_hh2 = (const float*)d_in[9];
    const float* b_ih2 = (const float*)d_in[10];
    const float* b_hh2 = (const float*)d_in[11];
    const float* w2    = (const float*)d_in[12];
    const float* bl2   = (const float*)d_in[13];
    float* out = (float*)d_out;

    k_gx1 <<<(L * 128 + 255) / 256, 256>>>(x, emb, w_ih1, b_ih1, b_hh1);
    k_fuse<<<(G2 * H1 + 255) / 256, 256>>>(w_ih2, w1, bl1, b_ih2, b_hh2);
    k_scan<<<2, 256>>>(w_hh1, w_hh2);
    dim3 g5((V + 127) / 128, 16);
    k_out <<<g5, 128>>>(w2, bl2, out);
}